// round 14
// baseline (speedup 1.0000x reference)
#include <cuda_runtime.h>
#include <cuda_fp16.h>
#include <cstdint>

// out[b,t,h] = (sum_c W[d[b],h,c]*f[b,t,c] + bias[d])*32 + pos[ts[b,t],h]
// Warp-specialized persistent kernel: 4 MMA warps (fp16 mma.sync, TMA ring)
// + 1 prep warp converting fp32->fp16 scratch for future batch-groups.

#define Bb 32
#define Tt 1024
#define Cc 512
#define Hh 1024
#define SCALE_F 32.0f

#define BM 128
#define BN 128
#define BK 64
#define NCH (Cc/BK)           // 8
#define STAGE_BYTES 32768
#define NSTAGE 3
#define SM_MBAR (NSTAGE * STAGE_BYTES)
#define SM_TOTAL (SM_MBAR + 64)

#define NTILES 2048
#define GRID_P 296
#define NGRP 4
#define UPG (1u<<20)          // prep units per group
#define HC4 131072            // H*C/4

#define NTHR 160              // 4 MMA warps + 1 prep warp

// Pre-swizzled chunk-major fp16 scratch: [b][chunk][row][128B]
__device__ __align__(128) __half g_fh[(size_t)Bb*Tt*Cc];
__device__ __align__(128) __half g_wh[(size_t)Bb*Hh*Cc];
__device__ unsigned g_ctr[NGRP];

__device__ __forceinline__ uint32_t s2u(const void* p) {
    uint32_t a;
    asm("{ .reg .u64 t; cvta.to.shared.u64 t, %1; cvt.u32.u64 %0, t; }" : "=r"(a) : "l"(p));
    return a;
}

__device__ __forceinline__ void ldmx4(uint32_t* r, uint32_t addr) {
    asm volatile("ldmatrix.sync.aligned.m8n8.x4.shared.b16 {%0,%1,%2,%3}, [%4];"
                 : "=r"(r[0]), "=r"(r[1]), "=r"(r[2]), "=r"(r[3]) : "r"(addr));
}

__device__ __forceinline__ void mma16816(float* d, const uint32_t* a, const uint32_t* b) {
    asm volatile(
        "mma.sync.aligned.m16n8k16.row.col.f32.f16.f16.f32 "
        "{%0,%1,%2,%3}, {%4,%5,%6,%7}, {%8,%9}, {%0,%1,%2,%3};"
        : "+f"(d[0]), "+f"(d[1]), "+f"(d[2]), "+f"(d[3])
        : "r"(a[0]), "r"(a[1]), "r"(a[2]), "r"(a[3]), "r"(b[0]), "r"(b[1]));
}

__device__ __forceinline__ uint32_t cvt2(float x, float y) {
    __half2 h = __floats2half2_rn(x, y);
    return *(uint32_t*)&h;
}

__device__ __forceinline__ void mbar_wait(uint32_t mb, uint32_t par) {
    uint32_t done;
    asm volatile("{\n .reg .pred p;\n mbarrier.try_wait.parity.acquire.cta.shared::cta.b64 p, [%1], %2;\n selp.b32 %0,1,0,p;\n}"
                 : "=r"(done) : "r"(mb), "r"(par) : "memory");
    if (!done) {
        asm volatile("{\n .reg .pred P1;\nWL_%=:\n mbarrier.try_wait.parity.acquire.cta.shared::cta.b64 P1, [%0], %1, 0x989680;\n @P1 bra.uni WD_%=;\n bra.uni WL_%=;\nWD_%=:\n}"
                     :: "r"(mb), "r"(par) : "memory");
    }
}

// barrier for the 4 MMA warps only (threads 0-127)
#define BAR_MMA() asm volatile("bar.sync 1, 128;" ::: "memory")

// One prep unit: pair of float4s fp32 -> one 16B fp16 unit, pre-swizzled.
__device__ __forceinline__ void prep_unit(uint32_t u, int grp,
        const float4* __restrict__ f, const float4* __restrict__ W,
        const int* __restrict__ dix) {
    const bool isF = u < (1u << 19);
    const int bl = (int)((u >> 16) & 7u);
    const uint32_t rem = u & 65535u;
    const int b = (grp << 3) + bl;
    float4 v0, v1;
    char* base;
    if (isF) {
        const size_t p = (((size_t)b << 16) + rem) * 2;
        v0 = f[p]; v1 = f[p + 1];
        base = (char*)g_fh;
    } else {
        const int d = dix[b];
        const size_t p = (size_t)d * HC4 + 2 * (size_t)rem;
        v0 = W[p]; v1 = W[p + 1];
        base = (char*)g_wh;
    }
    uint4 o;
    o.x = cvt2(v0.x, v0.y); o.y = cvt2(v0.z, v0.w);
    o.z = cvt2(v1.x, v1.y); o.w = cvt2(v1.z, v1.w);
    const uint32_t row = rem >> 6, jg = rem & 63u;
    const uint32_t chunk = jg >> 3, jp = jg & 7u;
    const size_t off = ((((size_t)(b * 8 + (int)chunk)) * 1024 + row) << 7)
                     + ((size_t)(jp ^ (row & 7u)) << 4);
    *(uint4*)(base + off) = o;
}

__global__ __launch_bounds__(NTHR, 2) void gemm_ws(
        const float4* __restrict__ f, const float4* __restrict__ W,
        const int* __restrict__ dix,
        const int* __restrict__ ts, const float* __restrict__ bias,
        const float* __restrict__ pos, float* __restrict__ out) {
    extern __shared__ char smem[];
    const uint32_t sb = s2u(smem);
    const int tid = threadIdx.x;
    const int bx = blockIdx.x;

    if (tid == 0) {
        #pragma unroll
        for (int s = 0; s < NSTAGE; s++)
            asm volatile("mbarrier.init.shared.b64 [%0], 1;"
                         :: "r"(sb + SM_MBAR + s * 8) : "memory");
    }
    __syncthreads();

    // per-CTA prep slice
    const uint32_t us = (uint32_t)(((uint64_t)bx * UPG) / GRID_P);
    const uint32_t ue = (uint32_t)(((uint64_t)(bx + 1) * UPG) / GRID_P);

    // ---- prologue: all 160 threads prep group 0, arrive, wait all ----
    #pragma unroll 1
    for (uint32_t u0 = us + tid; u0 < ue; u0 += 4 * NTHR) {
        prep_unit(u0, 0, f, W, dix);
        if (u0 + NTHR < ue) prep_unit(u0 + NTHR, 0, f, W, dix);
        if (u0 + 2 * NTHR < ue) prep_unit(u0 + 2 * NTHR, 0, f, W, dix);
        if (u0 + 3 * NTHR < ue) prep_unit(u0 + 3 * NTHR, 0, f, W, dix);
    }
    __threadfence();
    __syncthreads();
    if (tid == 0) {
        atomicAdd(&g_ctr[0], 1u);
        while (atomicAdd(&g_ctr[0], 0u) < (unsigned)GRID_P) {}
        __threadfence();
    }
    __syncthreads();

    const int w = tid >> 5, l = tid & 31;

    if (w == 4) {
        // ======== PREP WARP: convert groups 1..3, post counters ========
        #pragma unroll 1
        for (int tg = 1; tg < NGRP; tg++) {
            #pragma unroll 1
            for (uint32_t u = us + l; u < ue; u += 128) {
                prep_unit(u, tg, f, W, dix);
                if (u + 32 < ue) prep_unit(u + 32, tg, f, W, dix);
                if (u + 64 < ue) prep_unit(u + 64, tg, f, W, dix);
                if (u + 96 < ue) prep_unit(u + 96, tg, f, W, dix);
            }
            __threadfence();
            __syncwarp();
            if (l == 0) atomicAdd(&g_ctr[tg], 1u);
        }
        return;
    }

    // ======== MMA WARPS (threads 0-127) ========
    const int ntiles = (NTILES - 1 - bx) / GRID_P + 1;
    const int G = ntiles * NCH;

    auto issue = [&](int g) {
        const int tile = bx + (g >> 3) * GRID_P;
        const int chunk = g & 7;
        const int slot = g % NSTAGE;
        const int bb = tile >> 6;
        const int tt0 = ((tile >> 3) & 7) * BM;
        const int hh0 = (tile & 7) * BN;
        const uint32_t mb = sb + SM_MBAR + slot * 8;
        const uint32_t stb = sb + slot * STAGE_BYTES;
        const uint64_t srcA = (uint64_t)((const char*)g_fh
            + ((((size_t)bb * 8 + chunk) * 1024 + tt0) << 7));
        const uint64_t srcB = (uint64_t)((const char*)g_wh
            + ((((size_t)bb * 8 + chunk) * 1024 + hh0) << 7));
        asm volatile("mbarrier.arrive.expect_tx.shared.b64 _, [%0], %1;"
                     :: "r"(mb), "r"((uint32_t)STAGE_BYTES) : "memory");
        asm volatile("cp.async.bulk.shared::cluster.global.mbarrier::complete_tx::bytes "
                     "[%0], [%1], %2, [%3];"
                     :: "r"(stb), "l"(srcA), "r"(16384u), "r"(mb) : "memory");
        asm volatile("cp.async.bulk.shared::cluster.global.mbarrier::complete_tx::bytes "
                     "[%0], [%1], %2, [%3];"
                     :: "r"(stb + 16384u), "l"(srcB), "r"(16384u), "r"(mb) : "memory");
    };

    if (tid == 0) { issue(0); issue(1); issue(2); }   // tile 0 = group 0 (gated by prologue)

    const int wm = w >> 1, wn = w & 1;
    const int m0 = wm * 64, n0 = wn * 64;
    const int g4 = l >> 2, c4 = l & 3;

    const uint32_t swl = 4 * (l & 7);
    const uint32_t aRow = (uint32_t)(m0 + (l & 15)) * 128;
    const uint32_t aKsel = (l >> 4) * 4;
    const uint32_t bRow0 = (uint32_t)(n0 + ((l >> 4) * 8) + (l & 7)) * 128;
    const uint32_t bKsel = ((l >> 3) & 1) * 4;

    float acc[4][8][4] = {};
    int gated = 0;

    #pragma unroll 1
    for (int g = 0; g < G; g++) {
        const int slot = g % NSTAGE;
        mbar_wait(sb + SM_MBAR + slot * 8, (uint32_t)((g / NSTAGE) & 1));
        const uint32_t stA = sb + slot * STAGE_BYTES;
        const uint32_t stB = stA + 16384;
        #pragma unroll
        for (int ks = 0; ks < 4; ks++) {
            uint32_t a[4][4], bf[8][2];
            const uint32_t ak = (((uint32_t)(8 * ks) + aKsel) ^ swl) << 2;
            const uint32_t bk = (((uint32_t)(8 * ks) + bKsel) ^ swl) << 2;
            #pragma unroll
            for (int im = 0; im < 4; im++)
                ldmx4(a[im], stA + aRow + im * 2048 + ak);
            #pragma unroll
            for (int jp = 0; jp < 4; jp++) {
                uint32_t r[4];
                ldmx4(r, stB + bRow0 + jp * 2048 + bk);
                bf[2 * jp][0] = r[0]; bf[2 * jp][1] = r[1];
                bf[2 * jp + 1][0] = r[2]; bf[2 * jp + 1][1] = r[3];
            }
            #pragma unroll
            for (int im = 0; im < 4; im++)
                #pragma unroll
                for (int jn = 0; jn < 8; jn++)
                    mma16816(acc[im][jn], a[im], bf[jn]);
        }
        BAR_MMA();                           // MMA warps done reading slot

        if (tid == 0 && g + 3 < G) {
            const int tn = bx + ((g + 3) >> 3) * GRID_P;
            const int gn = tn >> 9;
            if (gn > gated) {
                while (atomicAdd(&g_ctr[gn], 0u) < (unsigned)GRID_P) {}
                gated = gn;
                __threadfence();
            }
            issue(g + 3);
        }

        if ((g & 7) == 7) {
            const int tile = bx + (g >> 3) * GRID_P;
            const int bb = tile >> 6;
            const int tt0 = ((tile >> 3) & 7) * BM;
            const int hh0 = (tile & 7) * BN;
            const int d = dix[bb];
            const float bv = bias[d];
            #pragma unroll
            for (int im = 0; im < 4; im++) {
                const int r0 = m0 + 16 * im + g4;
                const int tA = tt0 + r0, tB = tt0 + r0 + 8;
                const int pA = ts[bb * Tt + tA];
                const int pB = ts[bb * Tt + tB];
                const float* posA = pos + (size_t)pA * Hh;
                const float* posB = pos + (size_t)pB * Hh;
                float* outA = out + ((size_t)bb * Tt + tA) * Hh;
                float* outB = out + ((size_t)bb * Tt + tB) * Hh;
                #pragma unroll
                for (int jn = 0; jn < 8; jn++) {
                    const int col = hh0 + n0 + 8 * jn + 2 * c4;
                    float2 pv = *(const float2*)(posA + col);
                    float2 o;
                    o.x = (acc[im][jn][0] + bv) * SCALE_F + pv.x;
                    o.y = (acc[im][jn][1] + bv) * SCALE_F + pv.y;
                    *(float2*)(outA + col) = o;
                    pv = *(const float2*)(posB + col);
                    o.x = (acc[im][jn][2] + bv) * SCALE_F + pv.x;
                    o.y = (acc[im][jn][3] + bv) * SCALE_F + pv.y;
                    *(float2*)(outB + col) = o;
                }
            }
            #pragma unroll
            for (int im = 0; im < 4; im++)
                #pragma unroll
                for (int jn = 0; jn < 8; jn++)
                    #pragma unroll
                    for (int q = 0; q < 4; q++)
                        acc[im][jn][q] = 0.0f;
        }
    }
}

extern "C" void kernel_launch(void* const* d_in, const int* in_sizes, int n_in,
                              void* d_out, int out_size) {
    const float* features = (const float*)d_in[0];
    const int*   ts       = (const int*)d_in[1];
    const int*   date_idx = (const int*)d_in[2];
    const float* W        = (const float*)d_in[3];
    const float* bias     = (const float*)d_in[4];
    const float* pos      = (const float*)d_in[5];
    float* out = (float*)d_out;

    void* ctr = nullptr;
    cudaGetSymbolAddress(&ctr, g_ctr);
    cudaMemsetAsync(ctr, 0, sizeof(unsigned) * NGRP);

    cudaFuncSetAttribute(gemm_ws, cudaFuncAttributeMaxDynamicSharedMemorySize, SM_TOTAL);
    gemm_ws<<<GRID_P, NTHR, SM_TOTAL>>>(
        (const float4*)features, (const float4*)W, date_idx, ts, bias, pos, out);
}

// round 15
// speedup vs baseline: 1.7135x; 1.7135x over previous
#include <cuda_runtime.h>
#include <cuda_fp16.h>
#include <cstdint>

// out[b,t,h] = (sum_c W[d[b],h,c]*f[b,t,c] + bias[d])*32 + pos[ts[b,t],h]
// B=32,T=1024,C=512,H=1024. fp16 mma.sync GEMM (fp32 accum), TMA bulk loads
// from pre-swizzled chunk-major scratch. Persistent CTAs, 4 warps x 64x64,
// cross-chunk fragment double-buffering (hide mbar-wait + first-LDSM).

#define Bb 32
#define Tt 1024
#define Cc 512
#define Hh 1024
#define SCALE_F 32.0f

#define BM 128
#define BN 128
#define BK 64
#define NCH (Cc/BK)           // 8
#define STAGE_BYTES 32768
#define NSTAGE 3
#define SM_MBAR (NSTAGE * STAGE_BYTES)
#define SM_TOTAL (SM_MBAR + 64)

#define NTILES 2048
#define GRID_P 296

#define HC4 131072            // H*C/4
#define NPAIR_F 2097152       // B*T*C/8

// Pre-swizzled chunk-major fp16 scratch: [b][chunk][row][128B]
__device__ __align__(128) __half g_fh[(size_t)Bb*Tt*Cc];
__device__ __align__(128) __half g_wh[(size_t)Bb*Hh*Cc];

__device__ __forceinline__ uint32_t s2u(const void* p) {
    uint32_t a;
    asm("{ .reg .u64 t; cvta.to.shared.u64 t, %1; cvt.u32.u64 %0, t; }" : "=r"(a) : "l"(p));
    return a;
}

__device__ __forceinline__ void ldmx4(uint32_t* r, uint32_t addr) {
    asm volatile("ldmatrix.sync.aligned.m8n8.x4.shared.b16 {%0,%1,%2,%3}, [%4];"
                 : "=r"(r[0]), "=r"(r[1]), "=r"(r[2]), "=r"(r[3]) : "r"(addr));
}

__device__ __forceinline__ void mma16816(float* d, const uint32_t* a, const uint32_t* b) {
    asm volatile(
        "mma.sync.aligned.m16n8k16.row.col.f32.f16.f16.f32 "
        "{%0,%1,%2,%3}, {%4,%5,%6,%7}, {%8,%9}, {%0,%1,%2,%3};"
        : "+f"(d[0]), "+f"(d[1]), "+f"(d[2]), "+f"(d[3])
        : "r"(a[0]), "r"(a[1]), "r"(a[2]), "r"(a[3]), "r"(b[0]), "r"(b[1]));
}

__device__ __forceinline__ uint32_t cvt2(float x, float y) {
    __half2 h = __floats2half2_rn(x, y);
    return *(uint32_t*)&h;
}

// Prep: fp32 -> fp16, gathered (W), chunk-major pre-swizzled (R12-proven).
__global__ __launch_bounds__(256) void prep_all(const float4* __restrict__ f,
                                                const float4* __restrict__ W,
                                                const int* __restrict__ date_idx) {
    size_t idx = (size_t)blockIdx.x * 256 + threadIdx.x;   // 0 .. 2*NPAIR_F-1
    float4 v0, v1;
    char* base;
    int b, row, jg;
    if (idx < NPAIR_F) {
        b = (int)(idx >> 16);
        int rem = (int)(idx & 65535);
        row = rem >> 6; jg = rem & 63;
        v0 = f[2 * idx];
        v1 = f[2 * idx + 1];
        base = (char*)g_fh;
    } else {
        size_t k = idx - NPAIR_F;
        b = (int)(k >> 16);
        int rem = (int)(k & 65535);
        row = rem >> 6; jg = rem & 63;
        int d = date_idx[b];
        v0 = W[(size_t)d * HC4 + 2 * (size_t)rem];
        v1 = W[(size_t)d * HC4 + 2 * (size_t)rem + 1];
        base = (char*)g_wh;
    }
    uint4 o;
    o.x = cvt2(v0.x, v0.y);
    o.y = cvt2(v0.z, v0.w);
    o.z = cvt2(v1.x, v1.y);
    o.w = cvt2(v1.z, v1.w);
    int chunk = jg >> 3, jp = jg & 7;
    size_t off = ((((size_t)(b * 8 + chunk)) * 1024 + row) << 7)
               + ((uint32_t)(jp ^ (row & 7)) << 4);
    *(uint4*)(base + off) = o;
}

__device__ __forceinline__ void mbar_wait(uint32_t mb, uint32_t par) {
    uint32_t done;
    asm volatile("{\n .reg .pred p;\n mbarrier.try_wait.parity.acquire.cta.shared::cta.b64 p, [%1], %2;\n selp.b32 %0,1,0,p;\n}"
                 : "=r"(done) : "r"(mb), "r"(par) : "memory");
    if (!done) {
        asm volatile("{\n .reg .pred P1;\nWL_%=:\n mbarrier.try_wait.parity.acquire.cta.shared::cta.b64 P1, [%0], %1, 0x989680;\n @P1 bra.uni WD_%=;\n bra.uni WL_%=;\nWD_%=:\n}"
                     :: "r"(mb), "r"(par) : "memory");
    }
}

__global__ __launch_bounds__(128, 2) void gemm_main(const int* __restrict__ ts,
                                                    const int* __restrict__ date_idx,
                                                    const float* __restrict__ bias,
                                                    const float* __restrict__ pos,
                                                    float* __restrict__ out) {
    extern __shared__ char smem[];
    const uint32_t sb = s2u(smem);
    const int tid = threadIdx.x;
    const int bx = blockIdx.x;

    if (tid == 0) {
        #pragma unroll
        for (int s = 0; s < NSTAGE; s++)
            asm volatile("mbarrier.init.shared.b64 [%0], 1;"
                         :: "r"(sb + SM_MBAR + s * 8) : "memory");
    }
    __syncthreads();

    const int ntiles = (NTILES - 1 - bx) / GRID_P + 1;
    const int G = ntiles * NCH;

    auto issue = [&](int g) {
        const int tile = bx + (g >> 3) * GRID_P;
        const int chunk = g & 7;
        const int slot = g % NSTAGE;
        const int bb = tile >> 6;
        const int tt0 = ((tile >> 3) & 7) * BM;
        const int hh0 = (tile & 7) * BN;
        const uint32_t mb = sb + SM_MBAR + slot * 8;
        const uint32_t stb = sb + slot * STAGE_BYTES;
        const uint64_t srcA = (uint64_t)((const char*)g_fh
            + ((((size_t)bb * 8 + chunk) * 1024 + tt0) << 7));
        const uint64_t srcB = (uint64_t)((const char*)g_wh
            + ((((size_t)bb * 8 + chunk) * 1024 + hh0) << 7));
        asm volatile("mbarrier.arrive.expect_tx.shared.b64 _, [%0], %1;"
                     :: "r"(mb), "r"((uint32_t)STAGE_BYTES) : "memory");
        asm volatile("cp.async.bulk.shared::cluster.global.mbarrier::complete_tx::bytes "
                     "[%0], [%1], %2, [%3];"
                     :: "r"(stb), "l"(srcA), "r"(16384u), "r"(mb) : "memory");
        asm volatile("cp.async.bulk.shared::cluster.global.mbarrier::complete_tx::bytes "
                     "[%0], [%1], %2, [%3];"
                     :: "r"(stb + 16384u), "l"(srcB), "r"(16384u), "r"(mb) : "memory");
    };

    if (tid == 0) { issue(0); issue(1); issue(2); }

    const int w = tid >> 5, l = tid & 31;
    const int wm = w >> 1, wn = w & 1;
    const int m0 = wm * 64, n0 = wn * 64;
    const int g4 = l >> 2, c4 = l & 3;

    const uint32_t swl = 4 * (l & 7);
    const uint32_t aRow = (uint32_t)(m0 + (l & 15)) * 128;
    const uint32_t aKsel = (l >> 4) * 4;
    const uint32_t bRow0 = (uint32_t)(n0 + ((l >> 4) * 8) + (l & 7)) * 128;
    const uint32_t bKsel = ((l >> 3) & 1) * 4;

    float acc[4][8][4] = {};
    uint32_t a2[2][4][4], bf2[2][8][2];

    auto load_frags = [&](uint32_t stA, int ks, int buf) {
        const uint32_t stB = stA + 16384;
        const uint32_t ak = (((uint32_t)(8 * ks) + aKsel) ^ swl) << 2;
        const uint32_t bk = (((uint32_t)(8 * ks) + bKsel) ^ swl) << 2;
        #pragma unroll
        for (int im = 0; im < 4; im++)
            ldmx4(a2[buf][im], stA + aRow + im * 2048 + ak);
        #pragma unroll
        for (int jp = 0; jp < 4; jp++) {
            uint32_t r[4];
            ldmx4(r, stB + bRow0 + jp * 2048 + bk);
            bf2[buf][2 * jp][0] = r[0]; bf2[buf][2 * jp][1] = r[1];
            bf2[buf][2 * jp + 1][0] = r[2]; bf2[buf][2 * jp + 1][1] = r[3];
        }
    };

    // prologue: wait chunk 0, load its first fragments
    mbar_wait(sb + SM_MBAR, 0);
    load_frags(sb, 0, 0);

    #pragma unroll 1
    for (int g = 0; g < G; g++) {
        const uint32_t stA = sb + (g % NSTAGE) * STAGE_BYTES;
        #pragma unroll
        for (int ks = 0; ks < 4; ks++) {
            const int cur = ks & 1, nxt = cur ^ 1;
            if (ks < 3) {
                load_frags(stA, ks + 1, nxt);
            } else if (g + 1 < G) {
                // before the last HMMA batch: wait next chunk, prefetch its ks0
                const int g1 = g + 1;
                mbar_wait(sb + SM_MBAR + (g1 % NSTAGE) * 8,
                          (uint32_t)((g1 / NSTAGE) & 1));
                load_frags(sb + (g1 % NSTAGE) * STAGE_BYTES, 0, nxt);
            }
            #pragma unroll
            for (int im = 0; im < 4; im++)
                #pragma unroll
                for (int jn = 0; jn < 8; jn++)
                    mma16816(acc[im][jn], a2[cur][im], bf2[cur][jn]);
        }
        __syncthreads();                     // all warps done reading slot g
        if (tid == 0 && g + NSTAGE < G) issue(g + NSTAGE);

        if ((g & 7) == 7) {
            const int tile = bx + (g >> 3) * GRID_P;
            const int bb = tile >> 6;
            const int tt0 = ((tile >> 3) & 7) * BM;
            const int hh0 = (tile & 7) * BN;
            const int d = date_idx[bb];
            const float bv = bias[d];
            #pragma unroll
            for (int im = 0; im < 4; im++) {
                const int r0 = m0 + 16 * im + g4;
                const int tA = tt0 + r0, tB = tt0 + r0 + 8;
                const int pA = ts[bb * Tt + tA];
                const int pB = ts[bb * Tt + tB];
                const float* posA = pos + (size_t)pA * Hh;
                const float* posB = pos + (size_t)pB * Hh;
                float* outA = out + ((size_t)bb * Tt + tA) * Hh;
                float* outB = out + ((size_t)bb * Tt + tB) * Hh;
                #pragma unroll
                for (int jn = 0; jn < 8; jn++) {
                    const int col = hh0 + n0 + 8 * jn + 2 * c4;
                    float2 pv = *(const float2*)(posA + col);
                    float2 o;
                    o.x = (acc[im][jn][0] + bv) * SCALE_F + pv.x;
                    o.y = (acc[im][jn][1] + bv) * SCALE_F + pv.y;
                    *(float2*)(outA + col) = o;
                    pv = *(const float2*)(posB + col);
                    o.x = (acc[im][jn][2] + bv) * SCALE_F + pv.x;
                    o.y = (acc[im][jn][3] + bv) * SCALE_F + pv.y;
                    *(float2*)(outB + col) = o;
                }
            }
            #pragma unroll
            for (int im = 0; im < 4; im++)
                #pragma unroll
                for (int jn = 0; jn < 8; jn++)
                    #pragma unroll
                    for (int q = 0; q < 4; q++)
                        acc[im][jn][q] = 0.0f;
        }
    }
}

extern "C" void kernel_launch(void* const* d_in, const int* in_sizes, int n_in,
                              void* d_out, int out_size) {
    const float* features = (const float*)d_in[0];
    const int*   ts       = (const int*)d_in[1];
    const int*   date_idx = (const int*)d_in[2];
    const float* W        = (const float*)d_in[3];
    const float* bias     = (const float*)d_in[4];
    const float* pos      = (const float*)d_in[5];
    float* out = (float*)d_out;

    cudaFuncSetAttribute(gemm_main, cudaFuncAttributeMaxDynamicSharedMemorySize, SM_TOTAL);

    prep_all<<<(2 * NPAIR_F) / 256, 256>>>((const float4*)features, (const float4*)W, date_idx);
    gemm_main<<<GRID_P, 128, SM_TOTAL>>>(ts, date_idx, bias, pos, out);
}

// round 16
// speedup vs baseline: 2.0730x; 1.2098x over previous
#include <cuda_runtime.h>
#include <cuda_fp16.h>
#include <cstdint>

// out[b,t,h] = (sum_c W[d[b],h,c]*f[b,t,c] + bias[d])*32 + pos[ts[b,t],h]
// B=32,T=1024,C=512,H=1024. fp16 mma.sync GEMM (fp32 accum), TMA bulk loads
// from pre-swizzled chunk-major scratch. Persistent CTAs, 4 warps x 64x64.
// W scratch keyed per-date with dedup; streaming epilogue stores.

#define Bb 32
#define Tt 1024
#define Cc 512
#define Hh 1024
#define SCALE_F 32.0f

#define BM 128
#define BN 128
#define BK 64
#define NCH (Cc/BK)           // 8
#define STAGE_BYTES 32768
#define NSTAGE 3
#define SM_MBAR (NSTAGE * STAGE_BYTES)
#define SM_TOTAL (SM_MBAR + 64)

#define NTILES 2048
#define GRID_P 296
#define NDATES 64

#define HC4 131072            // H*C/4
#define NPAIR_F 2097152       // B*T*C/8

// Pre-swizzled chunk-major fp16 scratch.
// features: [b][chunk][row][128B]; W: [date][chunk][row][128B]
__device__ __align__(128) __half g_fh[(size_t)Bb*Tt*Cc];
__device__ __align__(128) __half g_wh[(size_t)NDATES*Hh*Cc];

__device__ __forceinline__ uint32_t s2u(const void* p) {
    uint32_t a;
    asm("{ .reg .u64 t; cvta.to.shared.u64 t, %1; cvt.u32.u64 %0, t; }" : "=r"(a) : "l"(p));
    return a;
}

__device__ __forceinline__ void ldmx4(uint32_t* r, uint32_t addr) {
    asm volatile("ldmatrix.sync.aligned.m8n8.x4.shared.b16 {%0,%1,%2,%3}, [%4];"
                 : "=r"(r[0]), "=r"(r[1]), "=r"(r[2]), "=r"(r[3]) : "r"(addr));
}

__device__ __forceinline__ void mma16816(float* d, const uint32_t* a, const uint32_t* b) {
    asm volatile(
        "mma.sync.aligned.m16n8k16.row.col.f32.f16.f16.f32 "
        "{%0,%1,%2,%3}, {%4,%5,%6,%7}, {%8,%9}, {%0,%1,%2,%3};"
        : "+f"(d[0]), "+f"(d[1]), "+f"(d[2]), "+f"(d[3])
        : "r"(a[0]), "r"(a[1]), "r"(a[2]), "r"(a[3]), "r"(b[0]), "r"(b[1]));
}

__device__ __forceinline__ uint32_t cvt2(float x, float y) {
    __half2 h = __floats2half2_rn(x, y);
    return *(uint32_t*)&h;
}

__device__ __forceinline__ void stg_cs2(float* p, float x, float y) {
    asm volatile("st.global.cs.v2.f32 [%0], {%1,%2};" :: "l"(p), "f"(x), "f"(y) : "memory");
}

// Prep: fp32 -> fp16, chunk-major pre-swizzled. W is converted per unique
// date (b skips if a smaller b' has the same date). One 16B store per thread.
__global__ __launch_bounds__(256) void prep_all(const float4* __restrict__ f,
                                                const float4* __restrict__ W,
                                                const int* __restrict__ date_idx) {
    size_t idx = (size_t)blockIdx.x * 256 + threadIdx.x;   // 0 .. 2*NPAIR_F-1
    float4 v0, v1;
    char* base;
    int key, row, jg;
    if (idx < NPAIR_F) {
        int b = (int)(idx >> 16);
        int rem = (int)(idx & 65535);
        row = rem >> 6; jg = rem & 63;
        v0 = f[2 * idx];
        v1 = f[2 * idx + 1];
        base = (char*)g_fh;
        key = b;
    } else {
        size_t k = idx - NPAIR_F;
        int b = (int)(k >> 16);
        int rem = (int)(k & 65535);
        row = rem >> 6; jg = rem & 63;
        int d = date_idx[b];
        // dedup: only the first b with this date converts it
        for (int b2 = 0; b2 < b; b2++)
            if (date_idx[b2] == d) return;
        v0 = W[(size_t)d * HC4 + 2 * (size_t)rem];
        v1 = W[(size_t)d * HC4 + 2 * (size_t)rem + 1];
        base = (char*)g_wh;
        key = d;
    }
    uint4 o;
    o.x = cvt2(v0.x, v0.y);
    o.y = cvt2(v0.z, v0.w);
    o.z = cvt2(v1.x, v1.y);
    o.w = cvt2(v1.z, v1.w);
    int chunk = jg >> 3, jp = jg & 7;
    size_t off = ((((size_t)(key * 8 + chunk)) * 1024 + row) << 7)
               + ((uint32_t)(jp ^ (row & 7)) << 4);
    *(uint4*)(base + off) = o;
}

__device__ __forceinline__ void mbar_wait(uint32_t mb, uint32_t par) {
    uint32_t done;
    asm volatile("{\n .reg .pred p;\n mbarrier.try_wait.parity.acquire.cta.shared::cta.b64 p, [%1], %2;\n selp.b32 %0,1,0,p;\n}"
                 : "=r"(done) : "r"(mb), "r"(par) : "memory");
    if (!done) {
        asm volatile("{\n .reg .pred P1;\nWL_%=:\n mbarrier.try_wait.parity.acquire.cta.shared::cta.b64 P1, [%0], %1, 0x989680;\n @P1 bra.uni WD_%=;\n bra.uni WL_%=;\nWD_%=:\n}"
                     :: "r"(mb), "r"(par) : "memory");
    }
}

__global__ __launch_bounds__(128, 2) void gemm_main(const int* __restrict__ ts,
                                                    const int* __restrict__ date_idx,
                                                    const float* __restrict__ bias,
                                                    const float* __restrict__ pos,
                                                    float* __restrict__ out) {
    extern __shared__ char smem[];
    const uint32_t sb = s2u(smem);
    const int tid = threadIdx.x;
    const int bx = blockIdx.x;

    if (tid == 0) {
        #pragma unroll
        for (int s = 0; s < NSTAGE; s++)
            asm volatile("mbarrier.init.shared.b64 [%0], 1;"
                         :: "r"(sb + SM_MBAR + s * 8) : "memory");
    }
    __syncthreads();

    const int ntiles = (NTILES - 1 - bx) / GRID_P + 1;
    const int G = ntiles * NCH;

    // issue global chunk g: tile = bx + (g/8)*GRID_P, chunk = g&7
    auto issue = [&](int g) {
        const int tile = bx + (g >> 3) * GRID_P;
        const int chunk = g & 7;
        const int slot = g % NSTAGE;
        const int bb = tile >> 6;
        const int tt0 = ((tile >> 3) & 7) * BM;
        const int hh0 = (tile & 7) * BN;
        const int dd = __ldg(&date_idx[bb]);
        const uint32_t mb = sb + SM_MBAR + slot * 8;
        const uint32_t stb = sb + slot * STAGE_BYTES;
        const uint64_t srcA = (uint64_t)((const char*)g_fh
            + ((((size_t)bb * 8 + chunk) * 1024 + tt0) << 7));
        const uint64_t srcB = (uint64_t)((const char*)g_wh
            + ((((size_t)dd * 8 + chunk) * 1024 + hh0) << 7));
        asm volatile("mbarrier.arrive.expect_tx.shared.b64 _, [%0], %1;"
                     :: "r"(mb), "r"((uint32_t)STAGE_BYTES) : "memory");
        asm volatile("cp.async.bulk.shared::cluster.global.mbarrier::complete_tx::bytes "
                     "[%0], [%1], %2, [%3];"
                     :: "r"(stb), "l"(srcA), "r"(16384u), "r"(mb) : "memory");
        asm volatile("cp.async.bulk.shared::cluster.global.mbarrier::complete_tx::bytes "
                     "[%0], [%1], %2, [%3];"
                     :: "r"(stb + 16384u), "l"(srcB), "r"(16384u), "r"(mb) : "memory");
    };

    if (tid == 0) { issue(0); issue(1); issue(2); }

    const int w = tid >> 5, l = tid & 31;
    const int wm = w >> 1, wn = w & 1;                    // 2x2 warps
    const int m0 = wm * 64, n0 = wn * 64;                 // warp tile 64x64
    const int g4 = l >> 2, c4 = l & 3;

    const uint32_t swl = 4 * (l & 7);
    const uint32_t aRow = (uint32_t)(m0 + (l & 15)) * 128;
    const uint32_t aKsel = (l >> 4) * 4;
    const uint32_t bRow0 = (uint32_t)(n0 + ((l >> 4) * 8) + (l & 7)) * 128;
    const uint32_t bKsel = ((l >> 3) & 1) * 4;

    float acc[4][8][4] = {};

    #pragma unroll 1
    for (int g = 0; g < G; g++) {
        const int slot = g % NSTAGE;
        mbar_wait(sb + SM_MBAR + slot * 8, (uint32_t)((g / NSTAGE) & 1));
        const uint32_t stA = sb + slot * STAGE_BYTES;
        const uint32_t stB = stA + 16384;
        #pragma unroll
        for (int ks = 0; ks < 4; ks++) {
            uint32_t a[4][4], bf[8][2];
            const uint32_t ak = (((uint32_t)(8 * ks) + aKsel) ^ swl) << 2;
            const uint32_t bk = (((uint32_t)(8 * ks) + bKsel) ^ swl) << 2;
            #pragma unroll
            for (int im = 0; im < 4; im++)
                ldmx4(a[im], stA + aRow + im * 2048 + ak);
            #pragma unroll
            for (int jp = 0; jp < 4; jp++) {
                uint32_t r[4];
                ldmx4(r, stB + bRow0 + jp * 2048 + bk);
                bf[2 * jp][0] = r[0]; bf[2 * jp][1] = r[1];
                bf[2 * jp + 1][0] = r[2]; bf[2 * jp + 1][1] = r[3];
            }
            #pragma unroll
            for (int im = 0; im < 4; im++)
                #pragma unroll
                for (int jn = 0; jn < 8; jn++)
                    mma16816(acc[im][jn], a[im], bf[jn]);
        }
        __syncthreads();                         // all warps done reading slot
        if (tid == 0 && g + NSTAGE < G) issue(g + NSTAGE);

        if ((g & 7) == 7) {
            // epilogue (TMA for next tile's chunks already in flight)
            const int tile = bx + (g >> 3) * GRID_P;
            const int bb = tile >> 6;
            const int tt0 = ((tile >> 3) & 7) * BM;
            const int hh0 = (tile & 7) * BN;
            const int d = date_idx[bb];
            const float bv = bias[d];
            #pragma unroll
            for (int im = 0; im < 4; im++) {
                const int r0 = m0 + 16 * im + g4;
                const int tA = tt0 + r0, tB = tt0 + r0 + 8;
                const int pA = ts[bb * Tt + tA];
                const int pB = ts[bb * Tt + tB];
                const float* posA = pos + (size_t)pA * Hh;
                const float* posB = pos + (size_t)pB * Hh;
                float* outA = out + ((size_t)bb * Tt + tA) * Hh;
                float* outB = out + ((size_t)bb * Tt + tB) * Hh;
                #pragma unroll
                for (int jn = 0; jn < 8; jn++) {
                    const int col = hh0 + n0 + 8 * jn + 2 * c4;
                    float2 pv = *(const float2*)(posA + col);
                    stg_cs2(outA + col,
                            (acc[im][jn][0] + bv) * SCALE_F + pv.x,
                            (acc[im][jn][1] + bv) * SCALE_F + pv.y);
                    pv = *(const float2*)(posB + col);
                    stg_cs2(outB + col,
                            (acc[im][jn][2] + bv) * SCALE_F + pv.x,
                            (acc[im][jn][3] + bv) * SCALE_F + pv.y);
                }
            }
            #pragma unroll
            for (int im = 0; im < 4; im++)
                #pragma unroll
                for (int jn = 0; jn < 8; jn++)
                    #pragma unroll
                    for (int q = 0; q < 4; q++)
                        acc[im][jn][q] = 0.0f;
        }
    }
}

extern "C" void kernel_launch(void* const* d_in, const int* in_sizes, int n_in,
                              void* d_out, int out_size) {
    const float* features = (const float*)d_in[0];
    const int*   ts       = (const int*)d_in[1];
    const int*   date_idx = (const int*)d_in[2];
    const float* W        = (const float*)d_in[3];
    const float* bias     = (const float*)d_in[4];
    const float* pos      = (const float*)d_in[5];
    float* out = (float*)d_out;

    cudaFuncSetAttribute(gemm_main, cudaFuncAttributeMaxDynamicSharedMemorySize, SM_TOTAL);

    prep_all<<<(2 * NPAIR_F) / 256, 256>>>((const float4*)features, (const float4*)W, date_idx);
    gemm_main<<<GRID_P, 128, SM_TOTAL>>>(ts, date_idx, bias, pos, out);
}

// round 17
// speedup vs baseline: 2.0887x; 1.0076x over previous
#include <cuda_runtime.h>
#include <cuda_fp16.h>
#include <cstdint>

// out[b,t,h] = (sum_c W[d[b],h,c]*f[b,t,c] + bias[d])*32 + pos[ts[b,t],h]
// B=32,T=1024,C=512,H=1024. fp16 mma.sync GEMM (fp32 accum), TMA bulk loads
// from pre-swizzled chunk-major scratch. Persistent CTAs, 4 warps x 64x64.
// W scratch keyed per-date (L2 reuse across same-date tiles); block-level
// dedup in prep; plain epilogue stores (R11-proven).

#define Bb 32
#define Tt 1024
#define Cc 512
#define Hh 1024
#define SCALE_F 32.0f

#define BM 128
#define BN 128
#define BK 64
#define NCH (Cc/BK)           // 8
#define STAGE_BYTES 32768
#define NSTAGE 3
#define SM_MBAR (NSTAGE * STAGE_BYTES)
#define SM_TOTAL (SM_MBAR + 64)

#define NTILES 2048
#define GRID_P 296
#define NDATES 64

#define HC4 131072            // H*C/4
#define NPAIR_F 2097152       // B*T*C/8
#define PREP_BLKS 16384       // 8192 feature blocks + 8192 W blocks

// Pre-swizzled chunk-major fp16 scratch.
// features: [b][chunk][row][128B]; W: [date][chunk][row][128B]
__device__ __align__(128) __half g_fh[(size_t)Bb*Tt*Cc];
__device__ __align__(128) __half g_wh[(size_t)NDATES*Hh*Cc];

__device__ __forceinline__ uint32_t s2u(const void* p) {
    uint32_t a;
    asm("{ .reg .u64 t; cvta.to.shared.u64 t, %1; cvt.u32.u64 %0, t; }" : "=r"(a) : "l"(p));
    return a;
}

__device__ __forceinline__ void ldmx4(uint32_t* r, uint32_t addr) {
    asm volatile("ldmatrix.sync.aligned.m8n8.x4.shared.b16 {%0,%1,%2,%3}, [%4];"
                 : "=r"(r[0]), "=r"(r[1]), "=r"(r[2]), "=r"(r[3]) : "r"(addr));
}

__device__ __forceinline__ void mma16816(float* d, const uint32_t* a, const uint32_t* b) {
    asm volatile(
        "mma.sync.aligned.m16n8k16.row.col.f32.f16.f16.f32 "
        "{%0,%1,%2,%3}, {%4,%5,%6,%7}, {%8,%9}, {%0,%1,%2,%3};"
        : "+f"(d[0]), "+f"(d[1]), "+f"(d[2]), "+f"(d[3])
        : "r"(a[0]), "r"(a[1]), "r"(a[2]), "r"(a[3]), "r"(b[0]), "r"(b[1]));
}

__device__ __forceinline__ uint32_t cvt2(float x, float y) {
    __half2 h = __floats2half2_rn(x, y);
    return *(uint32_t*)&h;
}

// Prep: fp32 -> fp16, chunk-major pre-swizzled.
// Blocks [0,8192): features (b = blk>>8). Blocks [8192,16384): W, with
// block-level dedup — only the first b carrying each date converts it.
__global__ __launch_bounds__(256) void prep_all(const float4* __restrict__ f,
                                                const float4* __restrict__ W,
                                                const int* __restrict__ date_idx) {
    __shared__ int s_skip;
    const int blk = blockIdx.x;
    const int tid = threadIdx.x;
    const bool isF = blk < 8192;
    const int b = (blk >> 8) & 31;
    const uint32_t rem = (uint32_t)((blk & 255) * 256 + tid);   // 0..65535
    const uint32_t row = rem >> 6, jg = rem & 63u;
    const uint32_t chunk = jg >> 3, jp = jg & 7u;

    float4 v0, v1;
    char* base;
    int key;
    if (isF) {
        const size_t p = (((size_t)b << 16) + rem) * 2;
        v0 = f[p]; v1 = f[p + 1];
        base = (char*)g_fh;
        key = b;
    } else {
        const int d = date_idx[b];
        if (tid == 0) {
            int skip = 0;
            for (int b2 = 0; b2 < b; b2++)
                if (date_idx[b2] == d) { skip = 1; break; }
            s_skip = skip;
        }
        __syncthreads();
        if (s_skip) return;
        const size_t p = (size_t)d * HC4 + 2 * (size_t)rem;
        v0 = W[p]; v1 = W[p + 1];
        base = (char*)g_wh;
        key = d;
    }
    uint4 o;
    o.x = cvt2(v0.x, v0.y);
    o.y = cvt2(v0.z, v0.w);
    o.z = cvt2(v1.x, v1.y);
    o.w = cvt2(v1.z, v1.w);
    const size_t off = ((((size_t)(key * 8 + (int)chunk)) * 1024 + row) << 7)
                     + ((size_t)(jp ^ (row & 7u)) << 4);
    *(uint4*)(base + off) = o;
}

__device__ __forceinline__ void mbar_wait(uint32_t mb, uint32_t par) {
    uint32_t done;
    asm volatile("{\n .reg .pred p;\n mbarrier.try_wait.parity.acquire.cta.shared::cta.b64 p, [%1], %2;\n selp.b32 %0,1,0,p;\n}"
                 : "=r"(done) : "r"(mb), "r"(par) : "memory");
    if (!done) {
        asm volatile("{\n .reg .pred P1;\nWL_%=:\n mbarrier.try_wait.parity.acquire.cta.shared::cta.b64 P1, [%0], %1, 0x989680;\n @P1 bra.uni WD_%=;\n bra.uni WL_%=;\nWD_%=:\n}"
                     :: "r"(mb), "r"(par) : "memory");
    }
}

__global__ __launch_bounds__(128, 2) void gemm_main(const int* __restrict__ ts,
                                                    const int* __restrict__ date_idx,
                                                    const float* __restrict__ bias,
                                                    const float* __restrict__ pos,
                                                    float* __restrict__ out) {
    extern __shared__ char smem[];
    const uint32_t sb = s2u(smem);
    const int tid = threadIdx.x;
    const int bx = blockIdx.x;

    if (tid == 0) {
        #pragma unroll
        for (int s = 0; s < NSTAGE; s++)
            asm volatile("mbarrier.init.shared.b64 [%0], 1;"
                         :: "r"(sb + SM_MBAR + s * 8) : "memory");
    }
    __syncthreads();

    const int ntiles = (NTILES - 1 - bx) / GRID_P + 1;
    const int G = ntiles * NCH;

    auto issue = [&](int g) {
        const int tile = bx + (g >> 3) * GRID_P;
        const int chunk = g & 7;
        const int slot = g % NSTAGE;
        const int bb = tile >> 6;
        const int tt0 = ((tile >> 3) & 7) * BM;
        const int hh0 = (tile & 7) * BN;
        const int dd = __ldg(&date_idx[bb]);
        const uint32_t mb = sb + SM_MBAR + slot * 8;
        const uint32_t stb = sb + slot * STAGE_BYTES;
        const uint64_t srcA = (uint64_t)((const char*)g_fh
            + ((((size_t)bb * 8 + chunk) * 1024 + tt0) << 7));
        const uint64_t srcB = (uint64_t)((const char*)g_wh
            + ((((size_t)dd * 8 + chunk) * 1024 + hh0) << 7));
        asm volatile("mbarrier.arrive.expect_tx.shared.b64 _, [%0], %1;"
                     :: "r"(mb), "r"((uint32_t)STAGE_BYTES) : "memory");
        asm volatile("cp.async.bulk.shared::cluster.global.mbarrier::complete_tx::bytes "
                     "[%0], [%1], %2, [%3];"
                     :: "r"(stb), "l"(srcA), "r"(16384u), "r"(mb) : "memory");
        asm volatile("cp.async.bulk.shared::cluster.global.mbarrier::complete_tx::bytes "
                     "[%0], [%1], %2, [%3];"
                     :: "r"(stb + 16384u), "l"(srcB), "r"(16384u), "r"(mb) : "memory");
    };

    if (tid == 0) { issue(0); issue(1); issue(2); }

    const int w = tid >> 5, l = tid & 31;
    const int wm = w >> 1, wn = w & 1;                    // 2x2 warps
    const int m0 = wm * 64, n0 = wn * 64;                 // warp tile 64x64
    const int g4 = l >> 2, c4 = l & 3;

    const uint32_t swl = 4 * (l & 7);
    const uint32_t aRow = (uint32_t)(m0 + (l & 15)) * 128;
    const uint32_t aKsel = (l >> 4) * 4;
    const uint32_t bRow0 = (uint32_t)(n0 + ((l >> 4) * 8) + (l & 7)) * 128;
    const uint32_t bKsel = ((l >> 3) & 1) * 4;

    float acc[4][8][4] = {};

    #pragma unroll 1
    for (int g = 0; g < G; g++) {
        const int slot = g % NSTAGE;
        mbar_wait(sb + SM_MBAR + slot * 8, (uint32_t)((g / NSTAGE) & 1));
        const uint32_t stA = sb + slot * STAGE_BYTES;
        const uint32_t stB = stA + 16384;
        #pragma unroll
        for (int ks = 0; ks < 4; ks++) {
            uint32_t a[4][4], bf[8][2];
            const uint32_t ak = (((uint32_t)(8 * ks) + aKsel) ^ swl) << 2;
            const uint32_t bk = (((uint32_t)(8 * ks) + bKsel) ^ swl) << 2;
            #pragma unroll
            for (int im = 0; im < 4; im++)
                ldmx4(a[im], stA + aRow + im * 2048 + ak);
            #pragma unroll
            for (int jp = 0; jp < 4; jp++) {
                uint32_t r[4];
                ldmx4(r, stB + bRow0 + jp * 2048 + bk);
                bf[2 * jp][0] = r[0]; bf[2 * jp][1] = r[1];
                bf[2 * jp + 1][0] = r[2]; bf[2 * jp + 1][1] = r[3];
            }
            #pragma unroll
            for (int im = 0; im < 4; im++)
                #pragma unroll
                for (int jn = 0; jn < 8; jn++)
                    mma16816(acc[im][jn], a[im], bf[jn]);
        }
        __syncthreads();                         // all warps done reading slot
        if (tid == 0 && g + NSTAGE < G) issue(g + NSTAGE);

        if ((g & 7) == 7) {
            const int tile = bx + (g >> 3) * GRID_P;
            const int bb = tile >> 6;
            const int tt0 = ((tile >> 3) & 7) * BM;
            const int hh0 = (tile & 7) * BN;
            const int d = date_idx[bb];
            const float bv = bias[d];
            #pragma unroll
            for (int im = 0; im < 4; im++) {
                const int r0 = m0 + 16 * im + g4;
                const int tA = tt0 + r0, tB = tt0 + r0 + 8;
                const int pA = ts[bb * Tt + tA];
                const int pB = ts[bb * Tt + tB];
                const float* posA = pos + (size_t)pA * Hh;
                const float* posB = pos + (size_t)pB * Hh;
                float* outA = out + ((size_t)bb * Tt + tA) * Hh;
                float* outB = out + ((size_t)bb * Tt + tB) * Hh;
                #pragma unroll
                for (int jn = 0; jn < 8; jn++) {
                    const int col = hh0 + n0 + 8 * jn + 2 * c4;
                    float2 pv = *(const float2*)(posA + col);
                    float2 o;
                    o.x = (acc[im][jn][0] + bv) * SCALE_F + pv.x;
                    o.y = (acc[im][jn][1] + bv) * SCALE_F + pv.y;
                    *(float2*)(outA + col) = o;
                    pv = *(const float2*)(posB + col);
                    o.x = (acc[im][jn][2] + bv) * SCALE_F + pv.x;
                    o.y = (acc[im][jn][3] + bv) * SCALE_F + pv.y;
                    *(float2*)(outB + col) = o;
                }
            }
            #pragma unroll
            for (int im = 0; im < 4; im++)
                #pragma unroll
                for (int jn = 0; jn < 8; jn++)
                    #pragma unroll
                    for (int q = 0; q < 4; q++)
                        acc[im][jn][q] = 0.0f;
        }
    }
}

extern "C" void kernel_launch(void* const* d_in, const int* in_sizes, int n_in,
                              void* d_out, int out_size) {
    const float* features = (const float*)d_in[0];
    const int*   ts       = (const int*)d_in[1];
    const int*   date_idx = (const int*)d_in[2];
    const float* W        = (const float*)d_in[3];
    const float* bias     = (const float*)d_in[4];
    const float* pos      = (const float*)d_in[5];
    float* out = (float*)d_out;

    cudaFuncSetAttribute(gemm_main, cudaFuncAttributeMaxDynamicSharedMemorySize, SM_TOTAL);

    prep_all<<<PREP_BLKS, 256>>>((const float4*)features, (const float4*)W, date_idx);
    gemm_main<<<GRID_P, 128, SM_TOTAL>>>(ts, date_idx, bias, pos, out);
}